// round 7
// baseline (speedup 1.0000x reference)
#include <cuda_runtime.h>
#include <cuda_bf16.h>
#include <mma.h>

using namespace nvcuda;

// ---------------------------------------------------------------------------
// CausalMLA — tf32 tensor-core GEMMs + fp32 attention
//   B=2, L=2048, D=2048, H=16, HD=128, LD=32
// ---------------------------------------------------------------------------

#define NTOK   4096      // B*L
#define DMODEL 2048
#define NHEAD  16
#define HDIM   128
#define LDIM   32
#define SEQ    2048
#define NBH    32        // B*H

// Scratch (static device globals; no runtime allocation allowed)
__device__ float g_Q [NTOK * DMODEL];
__device__ float g_K [NTOK * DMODEL];
__device__ float g_V [NTOK * DMODEL];
__device__ float g_qc[NBH * SEQ * LDIM];
__device__ float g_kc[NBH * SEQ * LDIM];
__device__ float g_vc[NBH * SEQ * LDIM];
__device__ float g_ac[NBH * SEQ * LDIM];
__device__ float g_a2[NTOK * DMODEL];

// ---------------------------------------------------------------------------
// tf32 tensor-core GEMM: C[M,N] = A[M,K] @ B[K,N] + bias[N]
// 128x128 block tile, BK=16, 8 warps (2x4), warp tile 64x32.
// wmma m16n16k8, fp32 accumulate. Double-buffered smem.
// ---------------------------------------------------------------------------
#define BM 128
#define BN 128
#define BK 16
#define APAD 8    // A row stride 24 floats = 96B (32B multiple)
#define BPAD 8    // B row stride 136 floats = 544B (32B multiple)

__global__ __launch_bounds__(256) void gemm_tf32_bias(
    const float* __restrict__ A, const float* __restrict__ B,
    const float* __restrict__ bias, float* __restrict__ C,
    int M, int N, int K)
{
    __shared__ __align__(32) float As[2][BM][BK + APAD];   // 2*12KB
    __shared__ __align__(32) float Bs[2][BK][BN + BPAD];   // 2*8.5KB

    const int tid = threadIdx.x;
    const int wid = tid >> 5;
    const int wr  = wid >> 2;            // warp row 0..1  (64 rows each)
    const int wc  = wid & 3;             // warp col 0..3  (32 cols each)
    const int m0  = blockIdx.y * BM;
    const int n0  = blockIdx.x * BN;

    // A tile load: 128 rows x 16 cols; 2 float4 per thread
    const int aRow = tid >> 2;           // 0..63
    const int aCol = (tid & 3) * 4;      // 0,4,8,12
    // B tile load: 16 rows x 128 cols; 2 float4 per thread
    const int bRow = tid >> 5;           // 0..7
    const int bCol = (tid & 31) * 4;     // 0..124

    const float* Aptr = A + (size_t)(m0 + aRow) * K + aCol;
    const float* Bptr = B + (size_t)bRow * N + n0 + bCol;

    float4 a0, a1, b0, b1;
    a0 = *(const float4*)(Aptr);
    a1 = *(const float4*)(Aptr + (size_t)64 * K);
    b0 = *(const float4*)(Bptr);
    b1 = *(const float4*)(Bptr + (size_t)8 * N);

    *(float4*)&As[0][aRow     ][aCol] = a0;
    *(float4*)&As[0][aRow + 64][aCol] = a1;
    *(float4*)&Bs[0][bRow     ][bCol] = b0;
    *(float4*)&Bs[0][bRow +  8][bCol] = b1;
    __syncthreads();

    wmma::fragment<wmma::accumulator, 16, 16, 8, float> c_frag[4][2];
    #pragma unroll
    for (int i = 0; i < 4; ++i)
        #pragma unroll
        for (int j = 0; j < 2; ++j)
            wmma::fill_fragment(c_frag[i][j], 0.0f);

    const int KT = K / BK;
    for (int t = 0; t < KT; ++t) {
        const int cur = t & 1;
        if (t + 1 < KT) {
            const float* Ap = Aptr + (t + 1) * BK;
            const float* Bp = Bptr + (size_t)(t + 1) * BK * N;
            a0 = *(const float4*)(Ap);
            a1 = *(const float4*)(Ap + (size_t)64 * K);
            b0 = *(const float4*)(Bp);
            b1 = *(const float4*)(Bp + (size_t)8 * N);
        }

        #pragma unroll
        for (int ks = 0; ks < 2; ++ks) {
            wmma::fragment<wmma::matrix_a, 16, 16, 8, wmma::precision::tf32,
                           wmma::row_major> a_frag[4];
            wmma::fragment<wmma::matrix_b, 16, 16, 8, wmma::precision::tf32,
                           wmma::row_major> b_frag[2];
            #pragma unroll
            for (int i = 0; i < 4; ++i) {
                wmma::load_matrix_sync(a_frag[i],
                    &As[cur][wr * 64 + i * 16][ks * 8], BK + APAD);
                #pragma unroll
                for (int e = 0; e < a_frag[i].num_elements; ++e)
                    a_frag[i].x[e] = wmma::__float_to_tf32(a_frag[i].x[e]);
            }
            #pragma unroll
            for (int j = 0; j < 2; ++j) {
                wmma::load_matrix_sync(b_frag[j],
                    &Bs[cur][ks * 8][wc * 32 + j * 16], BN + BPAD);
                #pragma unroll
                for (int e = 0; e < b_frag[j].num_elements; ++e)
                    b_frag[j].x[e] = wmma::__float_to_tf32(b_frag[j].x[e]);
            }
            #pragma unroll
            for (int i = 0; i < 4; ++i)
                #pragma unroll
                for (int j = 0; j < 2; ++j)
                    wmma::mma_sync(c_frag[i][j], a_frag[i], b_frag[j], c_frag[i][j]);
        }

        if (t + 1 < KT) {
            const int nxt = cur ^ 1;
            *(float4*)&As[nxt][aRow     ][aCol] = a0;
            *(float4*)&As[nxt][aRow + 64][aCol] = a1;
            *(float4*)&Bs[nxt][bRow     ][bCol] = b0;
            *(float4*)&Bs[nxt][bRow +  8][bCol] = b1;
        }
        __syncthreads();
    }

    // Bias: build a 16x128 tile with every row = bias[n0..n0+127], load as
    // accumulator fragments, add elementwise (fragment layouts match).
    {
        #pragma unroll
        for (int i = 0; i < 8; ++i) {
            const int idx = tid + i * 256;      // 0..2047
            const int r = idx >> 7, c = idx & 127;
            Bs[0][r][c] = bias[n0 + c];
        }
    }
    __syncthreads();

    wmma::fragment<wmma::accumulator, 16, 16, 8, float> bias_frag[2];
    #pragma unroll
    for (int j = 0; j < 2; ++j)
        wmma::load_matrix_sync(bias_frag[j], &Bs[0][0][wc * 32 + j * 16],
                               BN + BPAD, wmma::mem_row_major);

    #pragma unroll
    for (int i = 0; i < 4; ++i)
        #pragma unroll
        for (int j = 0; j < 2; ++j) {
            #pragma unroll
            for (int e = 0; e < c_frag[i][j].num_elements; ++e)
                c_frag[i][j].x[e] += bias_frag[j].x[e];
            wmma::store_matrix_sync(
                C + (size_t)(m0 + wr * 64 + i * 16) * N + n0 + wc * 32 + j * 16,
                c_frag[i][j], N, wmma::mem_row_major);
        }
}

// ---------------------------------------------------------------------------
// Compress: per (token, head) row, optional RoPE, project 128 -> 32.
// Output layout: out[(bh*SEQ + l)*32 + e], bh = b*16 + h.
// ---------------------------------------------------------------------------
template<bool ROPE>
__global__ __launch_bounds__(256) void compress_kernel(
    const float* __restrict__ X, const float* __restrict__ Wc,
    const float* __restrict__ bc, const float* __restrict__ cosT,
    const float* __restrict__ sinT, float* __restrict__ out)
{
    __shared__ float Wcs[HDIM * LDIM];
    __shared__ __align__(16) float rows[8][HDIM];

    const int tid  = threadIdx.x;
    const int lane = tid & 31;
    const int w    = tid >> 5;

    for (int i = tid; i < HDIM * LDIM; i += 256) Wcs[i] = Wc[i];
    __syncthreads();

    const int rid = blockIdx.x * 8 + w;
    const int t   = rid >> 4;
    const int h   = rid & 15;
    const int l   = t & (SEQ - 1);

    float4 v = *(const float4*)(X + (size_t)t * DMODEL + h * HDIM + lane * 4);
    if (ROPE) {
        const float c0 = cosT[l * 64 + lane * 2];
        const float s0 = sinT[l * 64 + lane * 2];
        const float c1 = cosT[l * 64 + lane * 2 + 1];
        const float s1 = sinT[l * 64 + lane * 2 + 1];
        float e0 = v.x, o0 = v.y, e1 = v.z, o1 = v.w;
        v.x = e0 * c0 - o0 * s0;
        v.y = e0 * s0 + o0 * c0;
        v.z = e1 * c1 - o1 * s1;
        v.w = e1 * s1 + o1 * c1;
    }
    *(float4*)&rows[w][lane * 4] = v;
    __syncwarp();

    float acc = bc[lane];
    #pragma unroll
    for (int d = 0; d < HDIM; ++d)
        acc += rows[w][d] * Wcs[d * LDIM + lane];

    const int bh = (t >> 11) * NHEAD + h;
    out[((size_t)bh * SEQ + l) * LDIM + lane] = acc;
}

// ---------------------------------------------------------------------------
// Causal flash attention, head-dim 32, fp32, online softmax, 16-key chunks.
// ---------------------------------------------------------------------------
__global__ __launch_bounds__(128) void flash_kernel(
    const float* __restrict__ QC, const float* __restrict__ KC,
    const float* __restrict__ VC, float* __restrict__ AC)
{
    __shared__ __align__(16) float kcs[128 * LDIM];
    __shared__ __align__(16) float vcs[128 * LDIM];

    const int tid = threadIdx.x;
    const int bh  = blockIdx.y;
    const int q0  = blockIdx.x * 128;
    const int qi  = q0 + tid;
    const float scale = 0.17677669529663687f;   // 1/sqrt(32)

    float qv[LDIM];
    {
        const float4* qp = (const float4*)(QC + ((size_t)bh * SEQ + qi) * LDIM);
        #pragma unroll
        for (int i = 0; i < 8; ++i) {
            float4 v = qp[i];
            qv[i * 4 + 0] = v.x * scale;
            qv[i * 4 + 1] = v.y * scale;
            qv[i * 4 + 2] = v.z * scale;
            qv[i * 4 + 3] = v.w * scale;
        }
    }

    float m = -1e30f, lsum = 0.f;
    float acc[LDIM];
    #pragma unroll
    for (int e = 0; e < LDIM; ++e) acc[e] = 0.f;

    const int ntiles = blockIdx.x + 1;
    for (int kt = 0; kt < ntiles; ++kt) {
        const int kstart = kt * 128;
        const float4* kg = (const float4*)(KC + ((size_t)bh * SEQ + kstart) * LDIM);
        const float4* vg = (const float4*)(VC + ((size_t)bh * SEQ + kstart) * LDIM);
        for (int idx = tid; idx < 128 * LDIM / 4; idx += 128) {
            ((float4*)kcs)[idx] = kg[idx];
            ((float4*)vcs)[idx] = vg[idx];
        }
        __syncthreads();

        const bool masked = (kt == blockIdx.x);

        #pragma unroll 1
        for (int c = 0; c < 8; ++c) {
            float sv[16];
            #pragma unroll
            for (int kk = 0; kk < 16; ++kk) {
                const float4* kr = (const float4*)(kcs + (c * 16 + kk) * LDIM);
                float d0 = 0.f, d1 = 0.f, d2 = 0.f, d3 = 0.f;
                #pragma unroll
                for (int e4 = 0; e4 < 8; ++e4) {
                    float4 kvv = kr[e4];
                    d0 += qv[e4 * 4 + 0] * kvv.x;
                    d1 += qv[e4 * 4 + 1] * kvv.y;
                    d2 += qv[e4 * 4 + 2] * kvv.z;
                    d3 += qv[e4 * 4 + 3] * kvv.w;
                }
                sv[kk] = (d0 + d1) + (d2 + d3);
            }
            if (masked) {
                #pragma unroll
                for (int kk = 0; kk < 16; ++kk)
                    if (kstart + c * 16 + kk > qi) sv[kk] = -1e30f;
            }
            float cmax = sv[0];
            #pragma unroll
            for (int kk = 1; kk < 16; ++kk) cmax = fmaxf(cmax, sv[kk]);
            const float mnew = fmaxf(m, cmax);
            const float r = __expf(m - mnew);
            lsum *= r;
            #pragma unroll
            for (int e = 0; e < LDIM; ++e) acc[e] *= r;
            #pragma unroll
            for (int kk = 0; kk < 16; ++kk) {
                const float p = __expf(sv[kk] - mnew);
                lsum += p;
                const float4* vr = (const float4*)(vcs + (c * 16 + kk) * LDIM);
                #pragma unroll
                for (int e4 = 0; e4 < 8; ++e4) {
                    float4 vv = vr[e4];
                    acc[e4 * 4 + 0] += p * vv.x;
                    acc[e4 * 4 + 1] += p * vv.y;
                    acc[e4 * 4 + 2] += p * vv.z;
                    acc[e4 * 4 + 3] += p * vv.w;
                }
            }
            m = mnew;
        }
        __syncthreads();
    }

    const float inv = 1.0f / lsum;
    float4* op = (float4*)(AC + ((size_t)bh * SEQ + qi) * LDIM);
    #pragma unroll
    for (int i = 0; i < 8; ++i) {
        float4 o;
        o.x = acc[i * 4 + 0] * inv;
        o.y = acc[i * 4 + 1] * inv;
        o.z = acc[i * 4 + 2] * inv;
        o.w = acc[i * 4 + 3] * inv;
        op[i] = o;
    }
}

// ---------------------------------------------------------------------------
// Decompress 32 -> 128 with Wd + bd, transpose [bh][l] -> [b,l][h].
// ---------------------------------------------------------------------------
__global__ __launch_bounds__(256) void decompress_kernel(
    const float* __restrict__ AC, const float* __restrict__ Wd,
    const float* __restrict__ bd, float* __restrict__ OUT)
{
    __shared__ float Wds[LDIM * HDIM];
    __shared__ float as[8][LDIM];

    const int tid = threadIdx.x;
    for (int i = tid; i < LDIM * HDIM; i += 256) Wds[i] = Wd[i];
    {
        const int r = tid >> 5, e = tid & 31;
        const int gr = blockIdx.x * 8 + r;
        as[r][e] = AC[(size_t)gr * LDIM + e];
    }
    __syncthreads();

    #pragma unroll
    for (int i = 0; i < 4; ++i) {
        const int idx = tid + i * 256;
        const int r = idx >> 7, d = idx & 127;
        float acc = bd[d];
        #pragma unroll
        for (int e = 0; e < LDIM; ++e)
            acc += as[r][e] * Wds[e * HDIM + d];
        const int gr = blockIdx.x * 8 + r;
        const int bh = gr >> 11;
        const int l  = gr & (SEQ - 1);
        const int b  = bh >> 4, h = bh & 15;
        OUT[((size_t)(b * SEQ + l)) * DMODEL + h * HDIM + d] = acc;
    }
}

// ---------------------------------------------------------------------------
// Launch
// ---------------------------------------------------------------------------
extern "C" void kernel_launch(void* const* d_in, const int* in_sizes, int n_in,
                              void* d_out, int out_size)
{
    const float* x    = (const float*)d_in[0];
    const float* cosT = (const float*)d_in[1];
    const float* sinT = (const float*)d_in[2];
    const float* Wq   = (const float*)d_in[3];
    const float* bq   = (const float*)d_in[4];
    const float* Wk   = (const float*)d_in[5];
    const float* bk   = (const float*)d_in[6];
    const float* Wv   = (const float*)d_in[7];
    const float* bv   = (const float*)d_in[8];
    const float* Wqc  = (const float*)d_in[9];
    const float* bqc  = (const float*)d_in[10];
    const float* Wkc  = (const float*)d_in[11];
    const float* bkc  = (const float*)d_in[12];
    const float* Wvc  = (const float*)d_in[13];
    const float* bvc  = (const float*)d_in[14];
    const float* Wd   = (const float*)d_in[15];
    const float* bd   = (const float*)d_in[16];
    const float* Wo   = (const float*)d_in[17];
    const float* bo   = (const float*)d_in[18];
    float* out = (float*)d_out;

    float *Q, *Kb, *Vb, *qc, *kc, *vc, *ac, *a2;
    cudaGetSymbolAddress((void**)&Q,  g_Q);
    cudaGetSymbolAddress((void**)&Kb, g_K);
    cudaGetSymbolAddress((void**)&Vb, g_V);
    cudaGetSymbolAddress((void**)&qc, g_qc);
    cudaGetSymbolAddress((void**)&kc, g_kc);
    cudaGetSymbolAddress((void**)&vc, g_vc);
    cudaGetSymbolAddress((void**)&ac, g_ac);
    cudaGetSymbolAddress((void**)&a2, g_a2);

    dim3 gg(DMODEL / 128, NTOK / 128);   // (16, 32)

    gemm_tf32_bias<<<gg, 256>>>(x, Wq, bq, Q,  NTOK, DMODEL, DMODEL);
    gemm_tf32_bias<<<gg, 256>>>(x, Wk, bk, Kb, NTOK, DMODEL, DMODEL);
    gemm_tf32_bias<<<gg, 256>>>(x, Wv, bv, Vb, NTOK, DMODEL, DMODEL);

    const int nblocks = (NTOK * NHEAD) / 8;   // 8192
    compress_kernel<true ><<<nblocks, 256>>>(Q,  Wqc, bqc, cosT, sinT, qc);
    compress_kernel<true ><<<nblocks, 256>>>(Kb, Wkc, bkc, cosT, sinT, kc);
    compress_kernel<false><<<nblocks, 256>>>(Vb, Wvc, bvc, cosT, sinT, vc);

    flash_kernel<<<dim3(SEQ / 128, NBH), 128>>>(qc, kc, vc, ac);

    decompress_kernel<<<nblocks, 256>>>(ac, Wd, bd, a2);

    gemm_tf32_bias<<<gg, 256>>>(a2, Wo, bo, out, NTOK, DMODEL, DMODEL);
}

// round 12
// speedup vs baseline: 1.4732x; 1.4732x over previous
#include <cuda_runtime.h>
#include <cuda_bf16.h>

// ---------------------------------------------------------------------------
// CausalMLA — fp32, algebraically folded V and output paths
//   B=2, L=2048, D=2048, H=16, HD=128, LD=32
//
//  Q = x@Wq+bq ; K = x@Wk+bk                 (2x SGEMM 4096x2048x2048)
//  qc/kc = rope(Q/K) @ Wc + bc               (compress kernels)
//  vc = x @ WvE + bvE                        (SGEMM 4096x512x2048, folded)
//  flash attention (head-dim 32), out in [t, h*32+e] layout
//  out = attn_c @ WoE + boE                  (SGEMM 4096x2048x512, folded)
// ---------------------------------------------------------------------------

#define NTOK   4096
#define DMODEL 2048
#define NHEAD  16
#define HDIM   128
#define LDIM   32
#define SEQ    2048
#define NBH    32
#define CDIM   512      // NHEAD * LDIM

// Scratch (static device globals; no runtime allocation allowed)
__device__ float g_Q  [NTOK * DMODEL];
__device__ float g_K  [NTOK * DMODEL];
__device__ float g_qc [NBH * SEQ * LDIM];
__device__ float g_kc [NBH * SEQ * LDIM];
__device__ float g_vc2[NTOK * CDIM];     // [t, h*32+e]
__device__ float g_ac2[NTOK * CDIM];     // [t, h*32+e]
__device__ float g_WvE[DMODEL * CDIM];   // [d, h*32+e]
__device__ float g_WoE[CDIM * DMODEL];   // [h*32+e, n]
__device__ float g_bvE[CDIM];
__device__ float g_boE[DMODEL];

// ---------------------------------------------------------------------------
// Weight folding kernels
// ---------------------------------------------------------------------------
// WvE[d, h*32+e] = sum_dd Wv[d, h*128+dd] * Wvc[dd, e]
__global__ __launch_bounds__(256) void fold_v_kernel(
    const float* __restrict__ Wv, const float* __restrict__ Wvc,
    float* __restrict__ WvE)
{
    __shared__ float wc[HDIM * LDIM];    // 16 KB
    const int tid = threadIdx.x;
    const int h   = blockIdx.x;
    const int d0  = blockIdx.y * 128;
    for (int i = tid; i < HDIM * LDIM; i += 256) wc[i] = Wvc[i];
    __syncthreads();

    #pragma unroll
    for (int i = 0; i < 16; ++i) {
        const int idx = tid + i * 256;           // 0..4095
        const int r = idx >> 5, e = idx & 31;
        const float* wrow = Wv + (size_t)(d0 + r) * DMODEL + h * HDIM;
        float acc = 0.f;
        #pragma unroll 8
        for (int dd = 0; dd < HDIM; ++dd)
            acc += wrow[dd] * wc[dd * LDIM + e];
        WvE[(size_t)(d0 + r) * CDIM + h * LDIM + e] = acc;
    }
}

// WoE[h*32+e, n] = sum_d Wd[e, d] * Wo[h*128+d, n]
__global__ __launch_bounds__(256) void fold_o_kernel(
    const float* __restrict__ Wd, const float* __restrict__ Wo,
    float* __restrict__ WoE)
{
    __shared__ float wd[LDIM * HDIM];    // 16 KB
    const int tid = threadIdx.x;
    const int n0  = blockIdx.x * 128;
    const int h   = blockIdx.y;
    for (int i = tid; i < LDIM * HDIM; i += 256) wd[i] = Wd[i];
    __syncthreads();

    #pragma unroll
    for (int i = 0; i < 16; ++i) {
        const int idx = tid + i * 256;           // 0..4095
        const int e = idx >> 7, c = idx & 127;
        float acc = 0.f;
        #pragma unroll 8
        for (int d = 0; d < HDIM; ++d)
            acc += wd[e * HDIM + d] * Wo[(size_t)(h * HDIM + d) * DMODEL + n0 + c];
        WoE[(size_t)(h * LDIM + e) * DMODEL + n0 + c] = acc;
    }
}

// bvE[h*32+e] = bvc[e] + sum_dd bv[h*128+dd] * Wvc[dd, e]
__global__ __launch_bounds__(256) void fold_bv_kernel(
    const float* __restrict__ bv, const float* __restrict__ Wvc,
    const float* __restrict__ bvc, float* __restrict__ bvE)
{
    const int i = blockIdx.x * 256 + threadIdx.x;   // 0..511
    if (i >= CDIM) return;
    const int h = i >> 5, e = i & 31;
    float acc = bvc[e];
    for (int dd = 0; dd < HDIM; ++dd)
        acc += bv[h * HDIM + dd] * Wvc[dd * LDIM + e];
    bvE[i] = acc;
}

// boE[n] = bo[n] + sum_m bd[m&127] * Wo[m, n]
__global__ __launch_bounds__(256) void fold_bo_kernel(
    const float* __restrict__ bd, const float* __restrict__ Wo,
    const float* __restrict__ bo, float* __restrict__ boE)
{
    const int n = blockIdx.x * 256 + threadIdx.x;   // 0..2047
    float acc = bo[n];
    for (int m = 0; m < DMODEL; ++m)
        acc += bd[m & 127] * Wo[(size_t)m * DMODEL + n];
    boE[n] = acc;
}

// ---------------------------------------------------------------------------
// SGEMM: C[M,N] = A[M,K] @ B[K,N] + bias[N]
// 128x128 block tile, BK=16, 8x8 per thread, 256 threads, smem double buffer.
// ---------------------------------------------------------------------------
__global__ __launch_bounds__(256) void sgemm_bias(
    const float* __restrict__ A, const float* __restrict__ B,
    const float* __restrict__ bias, float* __restrict__ C,
    int M, int N, int K)
{
    __shared__ __align__(16) float As[2][16][132];   // transposed, padded
    __shared__ __align__(16) float Bs[2][16][128];

    const int tid = threadIdx.x;
    const int tx  = tid & 15;
    const int ty  = tid >> 4;
    const int m0  = blockIdx.y * 128;
    const int n0  = blockIdx.x * 128;

    const int aRow = tid >> 2;          // 0..63
    const int aCol = (tid & 3) * 4;     // 0,4,8,12
    const int bRow = tid >> 5;          // 0..7
    const int bCol = (tid & 31) * 4;    // 0..124

    const float* Aptr = A + (size_t)(m0 + aRow) * K + aCol;
    const float* Bptr = B + (size_t)bRow * N + n0 + bCol;

    float4 a0, a1, b0, b1;
    a0 = *(const float4*)(Aptr);
    a1 = *(const float4*)(Aptr + (size_t)64 * K);
    b0 = *(const float4*)(Bptr);
    b1 = *(const float4*)(Bptr + (size_t)8 * N);

    As[0][aCol + 0][aRow]      = a0.x;
    As[0][aCol + 1][aRow]      = a0.y;
    As[0][aCol + 2][aRow]      = a0.z;
    As[0][aCol + 3][aRow]      = a0.w;
    As[0][aCol + 0][aRow + 64] = a1.x;
    As[0][aCol + 1][aRow + 64] = a1.y;
    As[0][aCol + 2][aRow + 64] = a1.z;
    As[0][aCol + 3][aRow + 64] = a1.w;
    *(float4*)&Bs[0][bRow][bCol]     = b0;
    *(float4*)&Bs[0][bRow + 8][bCol] = b1;
    __syncthreads();

    float acc[8][8];
    #pragma unroll
    for (int i = 0; i < 8; ++i)
        #pragma unroll
        for (int j = 0; j < 8; ++j) acc[i][j] = 0.f;

    const int KT = K >> 4;
    for (int t = 0; t < KT; ++t) {
        const int cur = t & 1;
        if (t + 1 < KT) {
            const float* Ap = Aptr + (t + 1) * 16;
            const float* Bp = Bptr + (size_t)(t + 1) * 16 * N;
            a0 = *(const float4*)(Ap);
            a1 = *(const float4*)(Ap + (size_t)64 * K);
            b0 = *(const float4*)(Bp);
            b1 = *(const float4*)(Bp + (size_t)8 * N);
        }

        #pragma unroll
        for (int k = 0; k < 16; ++k) {
            float4 ra0 = *(const float4*)&As[cur][k][ty * 8];
            float4 ra1 = *(const float4*)&As[cur][k][ty * 8 + 4];
            float4 rb0 = *(const float4*)&Bs[cur][k][tx * 8];
            float4 rb1 = *(const float4*)&Bs[cur][k][tx * 8 + 4];
            float ar[8] = {ra0.x, ra0.y, ra0.z, ra0.w, ra1.x, ra1.y, ra1.z, ra1.w};
            float br[8] = {rb0.x, rb0.y, rb0.z, rb0.w, rb1.x, rb1.y, rb1.z, rb1.w};
            #pragma unroll
            for (int i = 0; i < 8; ++i)
                #pragma unroll
                for (int j = 0; j < 8; ++j)
                    acc[i][j] += ar[i] * br[j];
        }

        if (t + 1 < KT) {
            const int nxt = cur ^ 1;
            As[nxt][aCol + 0][aRow]      = a0.x;
            As[nxt][aCol + 1][aRow]      = a0.y;
            As[nxt][aCol + 2][aRow]      = a0.z;
            As[nxt][aCol + 3][aRow]      = a0.w;
            As[nxt][aCol + 0][aRow + 64] = a1.x;
            As[nxt][aCol + 1][aRow + 64] = a1.y;
            As[nxt][aCol + 2][aRow + 64] = a1.z;
            As[nxt][aCol + 3][aRow + 64] = a1.w;
            *(float4*)&Bs[nxt][bRow][bCol]     = b0;
            *(float4*)&Bs[nxt][bRow + 8][bCol] = b1;
        }
        __syncthreads();
    }

    const int row = m0 + ty * 8;
    const int col = n0 + tx * 8;
    float4 bv0 = *(const float4*)(bias + col);
    float4 bv1 = *(const float4*)(bias + col + 4);
    #pragma unroll
    for (int i = 0; i < 8; ++i) {
        float4 o0 = make_float4(acc[i][0] + bv0.x, acc[i][1] + bv0.y,
                                acc[i][2] + bv0.z, acc[i][3] + bv0.w);
        float4 o1 = make_float4(acc[i][4] + bv1.x, acc[i][5] + bv1.y,
                                acc[i][6] + bv1.z, acc[i][7] + bv1.w);
        *(float4*)(C + (size_t)(row + i) * N + col)     = o0;
        *(float4*)(C + (size_t)(row + i) * N + col + 4) = o1;
    }
}

// ---------------------------------------------------------------------------
// Compress: per (token, head) row of X[NTOK, DMODEL], apply RoPE,
// project 128 -> 32.  out[(bh*SEQ + l)*32 + e], bh = b*16 + h.
// ---------------------------------------------------------------------------
__global__ __launch_bounds__(256) void compress_rope_kernel(
    const float* __restrict__ X, const float* __restrict__ Wc,
    const float* __restrict__ bc, const float* __restrict__ cosT,
    const float* __restrict__ sinT, float* __restrict__ out)
{
    __shared__ float Wcs[HDIM * LDIM];
    __shared__ __align__(16) float rows[8][HDIM];

    const int tid  = threadIdx.x;
    const int lane = tid & 31;
    const int w    = tid >> 5;

    for (int i = tid; i < HDIM * LDIM; i += 256) Wcs[i] = Wc[i];
    __syncthreads();

    const int rid = blockIdx.x * 8 + w;
    const int t   = rid >> 4;
    const int h   = rid & 15;
    const int l   = t & (SEQ - 1);

    float4 v = *(const float4*)(X + (size_t)t * DMODEL + h * HDIM + lane * 4);
    {
        const float c0 = cosT[l * 64 + lane * 2];
        const float s0 = sinT[l * 64 + lane * 2];
        const float c1 = cosT[l * 64 + lane * 2 + 1];
        const float s1 = sinT[l * 64 + lane * 2 + 1];
        float e0 = v.x, o0 = v.y, e1 = v.z, o1 = v.w;
        v.x = e0 * c0 - o0 * s0;
        v.y = e0 * s0 + o0 * c0;
        v.z = e1 * c1 - o1 * s1;
        v.w = e1 * s1 + o1 * c1;
    }
    *(float4*)&rows[w][lane * 4] = v;
    __syncwarp();

    float acc = bc[lane];
    #pragma unroll
    for (int d = 0; d < HDIM; ++d)
        acc += rows[w][d] * Wcs[d * LDIM + lane];

    const int bh = (t >> 11) * NHEAD + h;
    out[((size_t)bh * SEQ + l) * LDIM + lane] = acc;
}

// ---------------------------------------------------------------------------
// Causal flash attention, head-dim 32, fp32, online softmax, 16-key chunks.
// Q/K in [bh, l, 32]; V and output in [t, h*32+e] (t = b*SEQ + l).
// ---------------------------------------------------------------------------
__global__ __launch_bounds__(128) void flash_kernel(
    const float* __restrict__ QC, const float* __restrict__ KC,
    const float* __restrict__ VC2, float* __restrict__ AC2)
{
    __shared__ __align__(16) float kcs[128 * LDIM];
    __shared__ __align__(16) float vcs[128 * LDIM];

    const int tid = threadIdx.x;
    const int bh  = blockIdx.y;
    const int b   = bh >> 4, h = bh & 15;
    const int q0  = blockIdx.x * 128;
    const int qi  = q0 + tid;
    const float scale = 0.17677669529663687f;   // 1/sqrt(32)

    const float* Vbase = VC2 + (size_t)b * SEQ * CDIM + h * LDIM;
    float*       Obase = AC2 + (size_t)b * SEQ * CDIM + h * LDIM;

    float qv[LDIM];
    {
        const float4* qp = (const float4*)(QC + ((size_t)bh * SEQ + qi) * LDIM);
        #pragma unroll
        for (int i = 0; i < 8; ++i) {
            float4 v = qp[i];
            qv[i * 4 + 0] = v.x * scale;
            qv[i * 4 + 1] = v.y * scale;
            qv[i * 4 + 2] = v.z * scale;
            qv[i * 4 + 3] = v.w * scale;
        }
    }

    float m = -1e30f, lsum = 0.f;
    float acc[LDIM];
    #pragma unroll
    for (int e = 0; e < LDIM; ++e) acc[e] = 0.f;

    const int ntiles = blockIdx.x + 1;
    for (int kt = 0; kt < ntiles; ++kt) {
        const int kstart = kt * 128;
        const float4* kg = (const float4*)(KC + ((size_t)bh * SEQ + kstart) * LDIM);
        for (int idx = tid; idx < 128 * LDIM / 4; idx += 128) {
            ((float4*)kcs)[idx] = kg[idx];
            const int r = idx >> 3, j = idx & 7;
            ((float4*)vcs)[idx] =
                *(const float4*)(Vbase + (size_t)(kstart + r) * CDIM + j * 4);
        }
        __syncthreads();

        const bool masked = (kt == blockIdx.x);

        #pragma unroll 1
        for (int c = 0; c < 8; ++c) {
            float sv[16];
            #pragma unroll
            for (int kk = 0; kk < 16; ++kk) {
                const float4* kr = (const float4*)(kcs + (c * 16 + kk) * LDIM);
                float d0 = 0.f, d1 = 0.f, d2 = 0.f, d3 = 0.f;
                #pragma unroll
                for (int e4 = 0; e4 < 8; ++e4) {
                    float4 kvv = kr[e4];
                    d0 += qv[e4 * 4 + 0] * kvv.x;
                    d1 += qv[e4 * 4 + 1] * kvv.y;
                    d2 += qv[e4 * 4 + 2] * kvv.z;
                    d3 += qv[e4 * 4 + 3] * kvv.w;
                }
                sv[kk] = (d0 + d1) + (d2 + d3);
            }
            if (masked) {
                #pragma unroll
                for (int kk = 0; kk < 16; ++kk)
                    if (kstart + c * 16 + kk > qi) sv[kk] = -1e30f;
            }
            float cmax = sv[0];
            #pragma unroll
            for (int kk = 1; kk < 16; ++kk) cmax = fmaxf(cmax, sv[kk]);
            const float mnew = fmaxf(m, cmax);
            const float r = __expf(m - mnew);
            lsum *= r;
            #pragma unroll
            for (int e = 0; e < LDIM; ++e) acc[e] *= r;
            #pragma unroll
            for (int kk = 0; kk < 16; ++kk) {
                const float p = __expf(sv[kk] - mnew);
                lsum += p;
                const float4* vr = (const float4*)(vcs + (c * 16 + kk) * LDIM);
                #pragma unroll
                for (int e4 = 0; e4 < 8; ++e4) {
                    float4 vv = vr[e4];
                    acc[e4 * 4 + 0] += p * vv.x;
                    acc[e4 * 4 + 1] += p * vv.y;
                    acc[e4 * 4 + 2] += p * vv.z;
                    acc[e4 * 4 + 3] += p * vv.w;
                }
            }
            m = mnew;
        }
        __syncthreads();
    }

    const float inv = 1.0f / lsum;
    #pragma unroll
    for (int i = 0; i < 8; ++i) {
        float4 o;
        o.x = acc[i * 4 + 0] * inv;
        o.y = acc[i * 4 + 1] * inv;
        o.z = acc[i * 4 + 2] * inv;
        o.w = acc[i * 4 + 3] * inv;
        *(float4*)(Obase + (size_t)qi * CDIM + i * 4) = o;
    }
}

// ---------------------------------------------------------------------------
// Launch
// ---------------------------------------------------------------------------
extern "C" void kernel_launch(void* const* d_in, const int* in_sizes, int n_in,
                              void* d_out, int out_size)
{
    const float* x    = (const float*)d_in[0];
    const float* cosT = (const float*)d_in[1];
    const float* sinT = (const float*)d_in[2];
    const float* Wq   = (const float*)d_in[3];
    const float* bq   = (const float*)d_in[4];
    const float* Wk   = (const float*)d_in[5];
    const float* bk   = (const float*)d_in[6];
    const float* Wv   = (const float*)d_in[7];
    const float* bv   = (const float*)d_in[8];
    const float* Wqc  = (const float*)d_in[9];
    const float* bqc  = (const float*)d_in[10];
    const float* Wkc  = (const float*)d_in[11];
    const float* bkc  = (const float*)d_in[12];
    const float* Wvc  = (const float*)d_in[13];
    const float* bvc  = (const float*)d_in[14];
    const float* Wd   = (const float*)d_in[15];
    const float* bd   = (const float*)d_in[16];
    const float* Wo   = (const float*)d_in[17];
    const float* bo   = (const float*)d_in[18];
    float* out = (float*)d_out;

    float *Q, *Kb, *qc, *kc, *vc2, *ac2, *WvE, *WoE, *bvE, *boE;
    cudaGetSymbolAddress((void**)&Q,   g_Q);
    cudaGetSymbolAddress((void**)&Kb,  g_K);
    cudaGetSymbolAddress((void**)&qc,  g_qc);
    cudaGetSymbolAddress((void**)&kc,  g_kc);
    cudaGetSymbolAddress((void**)&vc2, g_vc2);
    cudaGetSymbolAddress((void**)&ac2, g_ac2);
    cudaGetSymbolAddress((void**)&WvE, g_WvE);
    cudaGetSymbolAddress((void**)&WoE, g_WoE);
    cudaGetSymbolAddress((void**)&bvE, g_bvE);
    cudaGetSymbolAddress((void**)&boE, g_boE);

    // Fold weights
    fold_v_kernel <<<dim3(NHEAD, DMODEL / 128), 256>>>(Wv, Wvc, WvE);
    fold_o_kernel <<<dim3(DMODEL / 128, NHEAD), 256>>>(Wd, Wo, WoE);
    fold_bv_kernel<<<2, 256>>>(bv, Wvc, bvc, bvE);
    fold_bo_kernel<<<DMODEL / 256, 256>>>(bd, Wo, bo, boE);

    // Big GEMMs
    dim3 gg(DMODEL / 128, NTOK / 128);   // (16, 32)
    sgemm_bias<<<gg, 256>>>(x, Wq, bq, Q,  NTOK, DMODEL, DMODEL);
    sgemm_bias<<<gg, 256>>>(x, Wk, bk, Kb, NTOK, DMODEL, DMODEL);
    sgemm_bias<<<dim3(CDIM / 128, NTOK / 128), 256>>>(
        x, WvE, bvE, vc2, NTOK, CDIM, DMODEL);

    // RoPE + compression for Q, K
    const int nblocks = (NTOK * NHEAD) / 8;   // 8192
    compress_rope_kernel<<<nblocks, 256>>>(Q,  Wqc, bqc, cosT, sinT, qc);
    compress_rope_kernel<<<nblocks, 256>>>(Kb, Wkc, bkc, cosT, sinT, kc);

    // Attention
    flash_kernel<<<dim3(SEQ / 128, NBH), 128>>>(qc, kc, vc2, ac2);

    // Folded output GEMM
    sgemm_bias<<<gg, 256>>>(ac2, WoE, boE, out, NTOK, DMODEL, CDIM);
}